// round 14
// baseline (speedup 1.0000x reference)
#include <cuda_runtime.h>
#include <cuda_fp16.h>
#include <cstdint>

// ---------------------------------------------------------------------------
// ResidualBlock: y = feat@Wnin + subconv(bnrelu2(subconv(bnrelu1(feat),W1)),W2)
// N=100000, A=64, B=128, K=27. fp32 in/out.
// Engine: mma.sync m16n8k16 fp16 (HMMA), single pass, fp32 accum.
// Round-14: 256-site CTA tiles (512 threads, 16 warps = 8M x 2N) -> halves
// total CTA-stages; triple-buffered smem, one barrier per stage; activation
// buffers pre-permuted (A-fill = pure uint4 copy); fp16 mid path.
// Mask semantics: masked-off rows contribute TRUE zeros.
// ---------------------------------------------------------------------------

#define KK   27
#define AA   64
#define BB   128
#define NMAX 100000
#define PB   512

// ---------------- static device scratch ------------------------------------
// fp16 activation buffers as u32 (=channel-pair) arrays, fragment-slot order
__device__ __align__(16) uint32_t g_f16[(size_t)NMAX * 32];   // raw feat
__device__ __align__(16) uint32_t g_a16[(size_t)NMAX * 32];   // bnrelu1(feat)
__device__ __align__(16) uint32_t g_mraw[(size_t)NMAX * 64];  // conv1 out
__device__ __align__(16) uint32_t g_m16[(size_t)NMAX * 64];   // bnrelu2(mid)
__device__ int   g_gidx[KK * NMAX];                           // gather idx/-1
__device__ float g_ps[PB * BB], g_pq[PB * BB];
__device__ float g_s1[AA], g_b1[AA], g_s2[BB], g_b2[BB];
// packed fp16 weight planes (2560 u32 each, n*20 + pslot(p)); stage-linear
__device__ __align__(16) uint32_t g_W1p[KK * 2 * 2560];
__device__ __align__(16) uint32_t g_Wcat[(2 + KK * 4) * 2560]; // [Wnin|W2]

// pair p (0..15) -> interleaved slot so fragment reg pairs are adjacent
__host__ __device__ __forceinline__ int pslot(int p) {
    return (p >> 3) * 8 + ((p & 3) * 2) + ((p & 7) >> 2);
}
// inverse of pslot
__host__ __device__ __forceinline__ int ipslot(int q) {
    int qq = q & 7, base = q & 8;
    return base + ((qq & 1) ? 4 + (qq >> 1) : (qq >> 1));
}

// pack two fp32 -> f16x2 (low half = first arg)
__device__ __forceinline__ uint32_t cvt2(float lo, float hi) {
    uint32_t r;
    asm("cvt.rn.f16x2.f32 %0, %1, %2;" : "=r"(r) : "f"(hi), "f"(lo));
    return r;
}

// mma.sync m16n8k16 f16: a={a0.x,a1.x,a0.y,a1.y}, b={b.x,b.y}, d += a@b
__device__ __forceinline__ void mma_f16(float* d, uint2 a0, uint2 a1, uint2 b) {
    asm volatile(
        "mma.sync.aligned.m16n8k16.row.col.f32.f16.f16.f32 "
        "{%0,%1,%2,%3}, {%4,%5,%6,%7}, {%8,%9}, {%0,%1,%2,%3};"
        : "+f"(d[0]), "+f"(d[1]), "+f"(d[2]), "+f"(d[3])
        : "r"(a0.x), "r"(a1.x), "r"(a0.y), "r"(a1.y), "r"(b.x), "r"(b.y));
}

// ---------------- small kernels --------------------------------------------
// gather index precompute with per-block mask-dtype detection
__global__ void k_gidx(const int* __restrict__ nbr,
                       const void* __restrict__ mp, int N) {
    __shared__ int s_u8;
    int t = threadIdx.x;
    int i = blockIdx.x * 256 + t;
    int probe = (i < N) ? i : (N - 1);
    int ok = (((const unsigned char*)mp)[(size_t)probe * KK + KK / 2] != 0);
    int all = __syncthreads_and(ok);
    if (t == 0) s_u8 = all;
    __syncthreads();
    if (i >= N) return;
    const bool u8 = (s_u8 != 0);
    const unsigned char* m8  = (const unsigned char*)mp;
    const int*           m32 = (const int*)mp;
#pragma unroll
    for (int k = 0; k < KK; k++) {
        bool m = u8 ? (m8[(size_t)i * KK + k] != 0)
                    : (m32[(size_t)i * KK + k] != 0);
        g_gidx[k * N + i] = m ? nbr[(size_t)i * KK + k] : -1;
    }
}

// BN1 apply + raw convert, fused: feat fp32 -> g_a16 (bn) + g_f16 (raw),
// both fp16 PERMUTED (pair p at pslot(p) within each 16-u32 chunk).
__global__ void k_bn1(const float* __restrict__ x,
                      const float* __restrict__ scl,
                      const float* __restrict__ bia, int n16) {
    int i = blockIdx.x * blockDim.x + threadIdx.x;
    if (i >= n16) return;                 // i indexes float4 over N*16
    float4 v = ((const float4*)x)[i];
    int row = i >> 4, t = i & 15;
    int c = t * 4;                        // true channel base
    int cc = t >> 3, p0 = (2 * t) & 15;
    int base = row * 32 + cc * 16;
    int pos0 = base + pslot(p0), pos1 = base + pslot(p0 + 1);
    g_f16[pos0] = cvt2(v.x, v.y);
    g_f16[pos1] = cvt2(v.z, v.w);
    float4 w;
    w.x = fmaxf(fmaf(v.x, scl[c],     bia[c]),     0.f);
    w.y = fmaxf(fmaf(v.y, scl[c + 1], bia[c + 1]), 0.f);
    w.z = fmaxf(fmaf(v.z, scl[c + 2], bia[c + 2]), 0.f);
    w.w = fmaxf(fmaf(v.w, scl[c + 3], bia[c + 3]), 0.f);
    g_a16[pos0] = cvt2(w.x, w.y);
    g_a16[pos1] = cvt2(w.z, w.w);
}

// BN2 apply: g_mraw (fp16 permuted) -> g_m16; positions identity, scale
// arrays are STORAGE-indexed (fin2 does the gamma/beta index mapping).
__global__ void k_bn2(const float* __restrict__ scl,
                      const float* __restrict__ bia, int n32) {
    int i = blockIdx.x * blockDim.x + threadIdx.x;
    if (i >= n32) return;                 // i indexes uint2 over N*32
    uint2 x = ((const uint2*)g_mraw)[i];
    int c = (i & 31) * 4;                 // storage channel base
    float2 f0 = __half22float2(*(const __half2*)&x.x);
    float2 f1 = __half22float2(*(const __half2*)&x.y);
    f0.x = fmaxf(fmaf(f0.x, scl[c],     bia[c]),     0.f);
    f0.y = fmaxf(fmaf(f0.y, scl[c + 1], bia[c + 1]), 0.f);
    f1.x = fmaxf(fmaf(f1.x, scl[c + 2], bia[c + 2]), 0.f);
    f1.y = fmaxf(fmaf(f1.y, scl[c + 3], bia[c + 3]), 0.f);
    uint2 r;
    r.x = cvt2(f0.x, f0.y);
    r.y = cvt2(f1.x, f1.y);
    ((uint2*)g_m16)[i] = r;
}

// fp32 stats (BN1): block (CH, RG)
template <int CH, int RG>
__global__ void k_stats(const float* __restrict__ x, int N) {
    int c = threadIdx.x, r = threadIdx.y;
    float s = 0.f, q = 0.f;
    for (int i = blockIdx.x * RG + r; i < N; i += gridDim.x * RG) {
        float v = x[(size_t)i * CH + c];
        s += v; q += v * v;
    }
    __shared__ float sh[RG][CH];
    __shared__ float shq[RG][CH];
    sh[r][c] = s; shq[r][c] = q;
    __syncthreads();
    if (r == 0) {
#pragma unroll
        for (int j = 1; j < RG; j++) { s += sh[j][c]; q += shq[j][c]; }
        g_ps[blockIdx.x * CH + c] = s;
        g_pq[blockIdx.x * CH + c] = q;
    }
}

// fp16 stats (BN2) over g_mraw: block (64 positions, RG); 2 channels/thread
template <int RG>
__global__ void k_stats16(int N) {
    int pos = threadIdx.x, r = threadIdx.y;
    float sl = 0.f, ql = 0.f, sh2 = 0.f, qh = 0.f;
    for (int i = blockIdx.x * RG + r; i < N; i += gridDim.x * RG) {
        uint32_t w = g_mraw[(size_t)i * 64 + pos];
        float2 f = __half22float2(*(const __half2*)&w);
        sl += f.x; ql += f.x * f.x;
        sh2 += f.y; qh += f.y * f.y;
    }
    __shared__ float sa[RG][128];
    __shared__ float sb[RG][128];
    sa[r][pos * 2] = sl;  sa[r][pos * 2 + 1] = sh2;
    sb[r][pos * 2] = ql;  sb[r][pos * 2 + 1] = qh;
    __syncthreads();
    if (r == 0) {
        float s0 = sa[0][pos * 2], s1 = sa[0][pos * 2 + 1];
        float q0 = sb[0][pos * 2], q1 = sb[0][pos * 2 + 1];
#pragma unroll
        for (int j = 1; j < RG; j++) {
            s0 += sa[j][pos * 2]; s1 += sa[j][pos * 2 + 1];
            q0 += sb[j][pos * 2]; q1 += sb[j][pos * 2 + 1];
        }
        g_ps[blockIdx.x * 128 + pos * 2]     = s0;
        g_ps[blockIdx.x * 128 + pos * 2 + 1] = s1;
        g_pq[blockIdx.x * 128 + pos * 2]     = q0;
        g_pq[blockIdx.x * 128 + pos * 2 + 1] = q1;
    }
}

// finisher: MAP=true translates storage channel -> true channel for gamma/beta
template <int CH, bool MAP>
__global__ void k_fin(const float* __restrict__ gamma,
                      const float* __restrict__ beta,
                      float* __restrict__ scl, float* __restrict__ bia, int N) {
    int c = threadIdx.x, r = threadIdx.y;
    float s = 0.f, q = 0.f;
    for (int b = r; b < PB; b += 8) { s += g_ps[b * CH + c]; q += g_pq[b * CH + c]; }
    __shared__ float sh[8][CH];
    __shared__ float shq[8][CH];
    sh[r][c] = s; shq[r][c] = q;
    __syncthreads();
    if (r == 0) {
#pragma unroll
        for (int j = 1; j < 8; j++) { s += sh[j][c]; q += shq[j][c]; }
        float mu  = s / (float)N;
        float var = q / (float)N - mu * mu;
        if (var < 0.f) var = 0.f;
        float rs = rsqrtf(var + 1e-4f);
        int tc = c;
        if (MAP) {
            int cc = c >> 5, wi = c & 31, qn = wi >> 1, e = wi & 1;
            tc = cc * 32 + ipslot(qn) * 2 + e;
        }
        float sc = gamma[tc] * rs;
        scl[c] = sc;
        bia[c] = beta[tc] - mu * sc;
    }
}

// weight pack: transpose-to-[n][k], fp16, pslot layout, stage-linear planes
__global__ void k_wcvt(const float* __restrict__ W1, const float* __restrict__ W2,
                       const float* __restrict__ Wn) {
    const int T1 = KK * 2 * 128 * 16;
    const int T2 = T1 + KK * 4 * 128 * 16;
    const int T3 = T2 + 2 * 128 * 16;
    int idx = blockIdx.x * blockDim.x + threadIdx.x;
    if (idx >= T3) return;
    const float* src; uint32_t* dst; int n, p;
    if (idx < T1) {
        int k = idx / (2 * 128 * 16), r = idx % (2 * 128 * 16);
        int ch = r / (128 * 16), r2 = r % (128 * 16);
        n = r2 / 16; p = r2 % 16;
        src = W1 + (size_t)k * 64 * 128 + (size_t)(ch * 32 + 2 * p) * 128 + n;
        dst = g_W1p + (size_t)(k * 2 + ch) * 2560;
    } else if (idx < T2) {
        int i2 = idx - T1;
        int k = i2 / (4 * 128 * 16), r = i2 % (4 * 128 * 16);
        int ch = r / (128 * 16), r2 = r % (128 * 16);
        n = r2 / 16; p = r2 % 16;
        src = W2 + (size_t)k * 128 * 128 + (size_t)(ch * 32 + 2 * p) * 128 + n;
        dst = g_Wcat + (size_t)(2 + k * 4 + ch) * 2560;
    } else {
        int i2 = idx - T2;
        int ch = i2 / (128 * 16), r2 = i2 % (128 * 16);
        n = r2 / 16; p = r2 % 16;
        src = Wn + (size_t)(ch * 32 + 2 * p) * 128 + n;
        dst = g_Wcat + (size_t)ch * 2560;
    }
    float w0 = src[0], w1 = src[128];
    __half h0 = __float2half(w0);
    __half h1 = __float2half(w1);
    uint32_t hp = ((uint32_t)*(unsigned short*)&h1 << 16) |
                  (uint32_t)*(unsigned short*)&h0;
    dst[n * 20 + pslot(p)] = hp;
}

// ---------------- pure gather-GEMM conv kernel -------------------------------
// MODE 1: mraw = sum_k a16[gidx_k] @ W1[k]                 (54 stages, fp16)
// MODE 2: out  = f16 @ Wnin + sum_k m16[gidx_k] @ W2[k]    (110 st, fp32)
// CTA: 256 sites x 128 cols; 512 threads, 16 warps (8M x 2N); D in fp32 regs.
// Sources pre-permuted -> A-fill is a pure uint4 copy (2 LDG.128 + 2 STS.128).
// Triple-buffered smem, one barrier per stage.

#define BUFU32 (256 * 20 + 2560)             // A rows (pad 20) + B plane
#define SMEMB  (3 * BUFU32 * 4)              // 92160 bytes

template <int MODE>
__global__ void __launch_bounds__(512, 1) k_conv(
    const uint32_t* __restrict__ src32, uint32_t* __restrict__ mid32,
    float* __restrict__ outp, int N) {

    constexpr int S = (MODE == 1) ? (KK * 2) : (2 + KK * 4);

    extern __shared__ char sm[];

    const int tid = threadIdx.x;
    const int wid = tid >> 5, lane = tid & 31;
    const int qr = lane >> 2, qc = lane & 3;
    const int wm = wid >> 1, wn = wid & 1;           // wm 0..7, wn 0..1
    const int tile = blockIdx.x * 256;
    const int r = tid >> 1, h = tid & 1;             // r 0..255
    const int site = tile + r;

    float acc[2][8][4];
#pragma unroll
    for (int a = 0; a < 2; a++)
#pragma unroll
        for (int b = 0; b < 8; b++)
#pragma unroll
            for (int c = 0; c < 4; c++) acc[a][b][c] = 0.f;

    auto rowOf = [&](int s) -> int {
        if (site >= N) return -1;
        if (MODE == 2 && s < 2) return site;                 // NiN dense
        int k = (MODE == 1) ? (s >> 1) : ((s - 2) >> 2);
        return g_gidx[(size_t)k * N + site];
    };

    uint4 rA2[2];
    uint4 rB[2];
    int   srA, srN;

    auto ldA = [&](int s, int sr) {
        const uint32_t* sp; int stride, c16;
        if (MODE == 2 && s < 2) { sp = g_f16;  stride = 32; c16 = s * 16; }
        else if (MODE == 1)     { sp = src32;  stride = 32; c16 = (s & 1) * 16; }
        else                    { sp = src32;  stride = 64; c16 = ((s - 2) & 3) * 16; }
        const uint4* rp = (const uint4*)(sp + (size_t)sr * stride + c16 + h * 8);
        if (sr >= 0) { rA2[0] = rp[0]; rA2[1] = rp[1]; }
    };
    auto ldB = [&](int s) {
        const uint32_t* bp = (MODE == 1) ? (g_W1p + (size_t)s * 2560)
                                         : (g_Wcat + (size_t)s * 2560);
        const uint4* wp = (const uint4*)bp;
        rB[0] = wp[tid < 640 ? tid : 0];
        int i1 = tid + 512;
        if (i1 < 640) rB[1] = wp[i1];
    };
    auto stStage = [&](int buf) {
        uint32_t* Ab = (uint32_t*)(sm + buf * (BUFU32 * 4));
        uint32_t* Bb = Ab + 256 * 20;
        {
            uint4* bd = (uint4*)Bb;
            if (tid < 640) bd[tid] = rB[0];
            int i1 = tid + 512;
            if (i1 < 640) bd[i1] = rB[1];
        }
        uint4* Aq = (uint4*)(Ab + r * 20 + h * 8);
        if (srA >= 0) { Aq[0] = rA2[0]; Aq[1] = rA2[1]; }
        else {
            uint4 z = make_uint4(0u, 0u, 0u, 0u);
            Aq[0] = z; Aq[1] = z;
        }
    };

    // ---- prologue
    srA = rowOf(0);
    ldA(0, srA);
    ldB(0);
    stStage(0);
    srN = (S > 1) ? rowOf(1) : -1;
    if (S > 1) { ldA(1, srN); ldB(1); }
    srA = srN;
    srN = (S > 2) ? rowOf(2) : -1;
    __syncthreads();

    // ---- main loop: one barrier per stage
    int bufMMA = 0;
#pragma unroll 3
    for (int s = 0; s < S; s++) {
        const uint32_t* Ab = (const uint32_t*)(sm + bufMMA * (BUFU32 * 4));
        const uint32_t* Bb = Ab + 256 * 20;
#pragma unroll
        for (int g = 0; g < 2; g++) {
            uint2 a0[2], a1[2];
#pragma unroll
            for (int mt = 0; mt < 2; mt++) {
                int r0 = wm * 32 + mt * 16 + qr;
                a0[mt] = *(const uint2*)&Ab[r0 * 20 + g * 8 + qc * 2];
                a1[mt] = *(const uint2*)&Ab[(r0 + 8) * 20 + g * 8 + qc * 2];
            }
#pragma unroll
            for (int nt = 0; nt < 8; nt++) {
                int c0b = wn * 64 + nt * 8 + qr;
                uint2 bf = *(const uint2*)&Bb[c0b * 20 + g * 8 + qc * 2];
                mma_f16(acc[0][nt], a0[0], a1[0], bf);
                mma_f16(acc[1][nt], a0[1], a1[1], bf);
            }
        }

        int bufN = bufMMA + 1; if (bufN == 3) bufN = 0;
        if (s + 1 < S) stStage(bufN);
        if (s + 2 < S) {
            ldA(s + 2, srN);
            ldB(s + 2);
            srA = srN;
            if (s + 3 < S) srN = rowOf(s + 3);
        }
        __syncthreads();
        bufMMA = bufN;
    }

    // ---- epilogue
#pragma unroll
    for (int mt = 0; mt < 2; mt++) {
        int r0 = wm * 32 + mt * 16 + qr;
        int sA = tile + r0, sB = tile + r0 + 8;
#pragma unroll
        for (int nt = 0; nt < 8; nt++) {
            if (MODE == 1) {
                // fp16 permuted write: pair P at slot pslot(P&15) of chunk P>>4
                int P = wn * 32 + nt * 4 + qc;
                int pos = (P >> 4) * 16 + pslot(P & 15);
                if (sA < N)
                    mid32[(size_t)sA * 64 + pos] =
                        cvt2(acc[mt][nt][0], acc[mt][nt][1]);
                if (sB < N)
                    mid32[(size_t)sB * 64 + pos] =
                        cvt2(acc[mt][nt][2], acc[mt][nt][3]);
            } else {
                int col = wn * 64 + nt * 8 + qc * 2;
                if (sA < N)
                    *(float2*)(outp + (size_t)sA * BB + col) =
                        make_float2(acc[mt][nt][0], acc[mt][nt][1]);
                if (sB < N)
                    *(float2*)(outp + (size_t)sB * BB + col) =
                        make_float2(acc[mt][nt][2], acc[mt][nt][3]);
            }
        }
    }
}

// ---------------------------------------------------------------------------
extern "C" void kernel_launch(void* const* d_in, const int* in_sizes, int n_in,
                              void* d_out, int out_size) {
    const float* feat   = (const float*)d_in[0];
    const float* gamma1 = (const float*)d_in[1];
    const float* beta1  = (const float*)d_in[2];
    const float* W1     = (const float*)d_in[3];
    const float* gamma2 = (const float*)d_in[4];
    const float* beta2  = (const float*)d_in[5];
    const float* W2     = (const float*)d_in[6];
    const float* Wnin   = (const float*)d_in[7];
    const int*   nbr    = (const int*)d_in[8];
    const void*  mask   = d_in[9];
    float*       out    = (float*)d_out;

    const int N = in_sizes[0] / AA;

    float *p_s1, *p_b1, *p_s2, *p_b2;
    uint32_t *p_a16, *p_m16, *p_mraw;
    cudaGetSymbolAddress((void**)&p_s1,   g_s1);
    cudaGetSymbolAddress((void**)&p_b1,   g_b1);
    cudaGetSymbolAddress((void**)&p_s2,   g_s2);
    cudaGetSymbolAddress((void**)&p_b2,   g_b2);
    cudaGetSymbolAddress((void**)&p_a16,  g_a16);
    cudaGetSymbolAddress((void**)&p_m16,  g_m16);
    cudaGetSymbolAddress((void**)&p_mraw, g_mraw);

    cudaFuncSetAttribute(k_conv<1>,
                         cudaFuncAttributeMaxDynamicSharedMemorySize, SMEMB);
    cudaFuncSetAttribute(k_conv<2>,
                         cudaFuncAttributeMaxDynamicSharedMemorySize, SMEMB);

    const int gtiles = (N + 255) / 256;
    const int wtot   = KK * 2 * 128 * 16 + KK * 4 * 128 * 16 + 2 * 128 * 16;
    const int n16    = N * 16;    // float4s in feat
    const int n32    = N * 32;    // uint2s in mid

    // prep: gather index (with fused mask detect), weight pack
    k_gidx<<<(N + 255) / 256, 256>>>(nbr, mask, N);
    k_wcvt<<<(wtot + 255) / 256, 256>>>(W1, W2, Wnin);

    // BN1: stats on fp32 feat -> folded affine -> fused apply + raw convert
    k_stats<AA, 4><<<PB, dim3(AA, 4)>>>(feat, N);
    k_fin<AA, false><<<1, dim3(AA, 8)>>>(gamma1, beta1, p_s1, p_b1, N);
    k_bn1<<<(n16 + 255) / 256, 256>>>(feat, p_s1, p_b1, n16);

    // conv1 -> g_mraw (fp16, permuted)
    k_conv<1><<<gtiles, 512, SMEMB>>>(p_a16, p_mraw, nullptr, N);

    // BN2: stats on fp16 mid -> folded affine (gamma mapped) -> apply
    k_stats16<4><<<PB, dim3(64, 4)>>>(N);
    k_fin<BB, true><<<1, dim3(BB, 8)>>>(gamma2, beta2, p_s2, p_b2, N);
    k_bn2<<<(n32 + 255) / 256, 256>>>(p_s2, p_b2, n32);

    // conv2 (NiN fused as 2 leading dense stages) -> out (write-once fp32)
    k_conv<2><<<gtiles, 512, SMEMB>>>(p_m16, nullptr, out, N);
}

// round 15
// speedup vs baseline: 1.4826x; 1.4826x over previous
#include <cuda_runtime.h>
#include <cuda_fp16.h>
#include <cstdint>

// ---------------------------------------------------------------------------
// ResidualBlock: y = feat@Wnin + subconv(bnrelu2(subconv(bnrelu1(feat),W1)),W2)
// N=100000, A=64, B=128, K=27. fp32 in/out.
// Engine: mma.sync m16n8k16 fp16 (HMMA), single pass, fp32 accum.
// Round-15: conv path reverted to round-13 (128-site tiles, 256 thr, 2 CTA/SM,
// triple buffer, one barrier/stage — proven 774us). k_fin parallelized
// (1 block/channel) to remove the measured 2x ~20us grid=1 latency stall.
// Mask semantics: masked-off rows contribute TRUE zeros.
// ---------------------------------------------------------------------------

#define KK   27
#define AA   64
#define BB   128
#define NMAX 100000
#define PB   512

// ---------------- static device scratch ------------------------------------
// fp16 activation buffers as u32 (=channel-pair) arrays, fragment-slot order
__device__ __align__(16) uint32_t g_f16[(size_t)NMAX * 32];   // raw feat
__device__ __align__(16) uint32_t g_a16[(size_t)NMAX * 32];   // bnrelu1(feat)
__device__ __align__(16) uint32_t g_mraw[(size_t)NMAX * 64];  // conv1 out
__device__ __align__(16) uint32_t g_m16[(size_t)NMAX * 64];   // bnrelu2(mid)
__device__ int   g_gidx[KK * NMAX];                           // gather idx/-1
__device__ float g_ps[PB * BB], g_pq[PB * BB];
__device__ float g_s1[AA], g_b1[AA], g_s2[BB], g_b2[BB];
// packed fp16 weight planes (2560 u32 each, n*20 + pslot(p)); stage-linear
__device__ __align__(16) uint32_t g_W1p[KK * 2 * 2560];
__device__ __align__(16) uint32_t g_Wcat[(2 + KK * 4) * 2560]; // [Wnin|W2]

// pair p (0..15) -> interleaved slot so fragment reg pairs are adjacent
__host__ __device__ __forceinline__ int pslot(int p) {
    return (p >> 3) * 8 + ((p & 3) * 2) + ((p & 7) >> 2);
}
// inverse of pslot
__host__ __device__ __forceinline__ int ipslot(int q) {
    int qq = q & 7, base = q & 8;
    return base + ((qq & 1) ? 4 + (qq >> 1) : (qq >> 1));
}

// pack two fp32 -> f16x2 (low half = first arg)
__device__ __forceinline__ uint32_t cvt2(float lo, float hi) {
    uint32_t r;
    asm("cvt.rn.f16x2.f32 %0, %1, %2;" : "=r"(r) : "f"(hi), "f"(lo));
    return r;
}

// mma.sync m16n8k16 f16: a={a0.x,a1.x,a0.y,a1.y}, b={b.x,b.y}, d += a@b
__device__ __forceinline__ void mma_f16(float* d, uint2 a0, uint2 a1, uint2 b) {
    asm volatile(
        "mma.sync.aligned.m16n8k16.row.col.f32.f16.f16.f32 "
        "{%0,%1,%2,%3}, {%4,%5,%6,%7}, {%8,%9}, {%0,%1,%2,%3};"
        : "+f"(d[0]), "+f"(d[1]), "+f"(d[2]), "+f"(d[3])
        : "r"(a0.x), "r"(a1.x), "r"(a0.y), "r"(a1.y), "r"(b.x), "r"(b.y));
}

// ---------------- small kernels --------------------------------------------
// gather index precompute with per-block mask-dtype detection
__global__ void k_gidx(const int* __restrict__ nbr,
                       const void* __restrict__ mp, int N) {
    __shared__ int s_u8;
    int t = threadIdx.x;
    int i = blockIdx.x * 256 + t;
    int probe = (i < N) ? i : (N - 1);
    int ok = (((const unsigned char*)mp)[(size_t)probe * KK + KK / 2] != 0);
    int all = __syncthreads_and(ok);
    if (t == 0) s_u8 = all;
    __syncthreads();
    if (i >= N) return;
    const bool u8 = (s_u8 != 0);
    const unsigned char* m8  = (const unsigned char*)mp;
    const int*           m32 = (const int*)mp;
#pragma unroll
    for (int k = 0; k < KK; k++) {
        bool m = u8 ? (m8[(size_t)i * KK + k] != 0)
                    : (m32[(size_t)i * KK + k] != 0);
        g_gidx[k * N + i] = m ? nbr[(size_t)i * KK + k] : -1;
    }
}

// BN1 apply + raw convert, fused: feat fp32 -> g_a16 (bn) + g_f16 (raw),
// both fp16 PERMUTED (pair p at pslot(p) within each 16-u32 chunk).
__global__ void k_bn1(const float* __restrict__ x,
                      const float* __restrict__ scl,
                      const float* __restrict__ bia, int n16) {
    int i = blockIdx.x * blockDim.x + threadIdx.x;
    if (i >= n16) return;                 // i indexes float4 over N*16
    float4 v = ((const float4*)x)[i];
    int row = i >> 4, t = i & 15;
    int c = t * 4;                        // true channel base
    int cc = t >> 3, p0 = (2 * t) & 15;
    int base = row * 32 + cc * 16;
    int pos0 = base + pslot(p0), pos1 = base + pslot(p0 + 1);
    g_f16[pos0] = cvt2(v.x, v.y);
    g_f16[pos1] = cvt2(v.z, v.w);
    float4 w;
    w.x = fmaxf(fmaf(v.x, scl[c],     bia[c]),     0.f);
    w.y = fmaxf(fmaf(v.y, scl[c + 1], bia[c + 1]), 0.f);
    w.z = fmaxf(fmaf(v.z, scl[c + 2], bia[c + 2]), 0.f);
    w.w = fmaxf(fmaf(v.w, scl[c + 3], bia[c + 3]), 0.f);
    g_a16[pos0] = cvt2(w.x, w.y);
    g_a16[pos1] = cvt2(w.z, w.w);
}

// BN2 apply: g_mraw (fp16 permuted) -> g_m16; positions identity, scale
// arrays are STORAGE-indexed (fin2 does the gamma/beta index mapping).
__global__ void k_bn2(const float* __restrict__ scl,
                      const float* __restrict__ bia, int n32) {
    int i = blockIdx.x * blockDim.x + threadIdx.x;
    if (i >= n32) return;                 // i indexes uint2 over N*32
    uint2 x = ((const uint2*)g_mraw)[i];
    int c = (i & 31) * 4;                 // storage channel base
    float2 f0 = __half22float2(*(const __half2*)&x.x);
    float2 f1 = __half22float2(*(const __half2*)&x.y);
    f0.x = fmaxf(fmaf(f0.x, scl[c],     bia[c]),     0.f);
    f0.y = fmaxf(fmaf(f0.y, scl[c + 1], bia[c + 1]), 0.f);
    f1.x = fmaxf(fmaf(f1.x, scl[c + 2], bia[c + 2]), 0.f);
    f1.y = fmaxf(fmaf(f1.y, scl[c + 3], bia[c + 3]), 0.f);
    uint2 r;
    r.x = cvt2(f0.x, f0.y);
    r.y = cvt2(f1.x, f1.y);
    ((uint2*)g_m16)[i] = r;
}

// fp32 stats (BN1): block (CH, RG)
template <int CH, int RG>
__global__ void k_stats(const float* __restrict__ x, int N) {
    int c = threadIdx.x, r = threadIdx.y;
    float s = 0.f, q = 0.f;
    for (int i = blockIdx.x * RG + r; i < N; i += gridDim.x * RG) {
        float v = x[(size_t)i * CH + c];
        s += v; q += v * v;
    }
    __shared__ float sh[RG][CH];
    __shared__ float shq[RG][CH];
    sh[r][c] = s; shq[r][c] = q;
    __syncthreads();
    if (r == 0) {
#pragma unroll
        for (int j = 1; j < RG; j++) { s += sh[j][c]; q += shq[j][c]; }
        g_ps[blockIdx.x * CH + c] = s;
        g_pq[blockIdx.x * CH + c] = q;
    }
}

// fp16 stats (BN2) over g_mraw: block (64 positions, RG); 2 channels/thread
template <int RG>
__global__ void k_stats16(int N) {
    int pos = threadIdx.x, r = threadIdx.y;
    float sl = 0.f, ql = 0.f, sh2 = 0.f, qh = 0.f;
    for (int i = blockIdx.x * RG + r; i < N; i += gridDim.x * RG) {
        uint32_t w = g_mraw[(size_t)i * 64 + pos];
        float2 f = __half22float2(*(const __half2*)&w);
        sl += f.x; ql += f.x * f.x;
        sh2 += f.y; qh += f.y * f.y;
    }
    __shared__ float sa[RG][128];
    __shared__ float sb[RG][128];
    sa[r][pos * 2] = sl;  sa[r][pos * 2 + 1] = sh2;
    sb[r][pos * 2] = ql;  sb[r][pos * 2 + 1] = qh;
    __syncthreads();
    if (r == 0) {
        float s0 = sa[0][pos * 2], s1 = sa[0][pos * 2 + 1];
        float q0 = sb[0][pos * 2], q1 = sb[0][pos * 2 + 1];
#pragma unroll
        for (int j = 1; j < RG; j++) {
            s0 += sa[j][pos * 2]; s1 += sa[j][pos * 2 + 1];
            q0 += sb[j][pos * 2]; q1 += sb[j][pos * 2 + 1];
        }
        g_ps[blockIdx.x * 128 + pos * 2]     = s0;
        g_ps[blockIdx.x * 128 + pos * 2 + 1] = s1;
        g_pq[blockIdx.x * 128 + pos * 2]     = q0;
        g_pq[blockIdx.x * 128 + pos * 2 + 1] = q1;
    }
}

// PARALLEL finisher: ONE BLOCK PER CHANNEL (grid = CH, block = 256).
// Tree-reduces the PB=512 partials for its channel; ~4KB read per block.
// MAP=true translates storage channel -> true channel for gamma/beta.
template <int CH, bool MAP>
__global__ void k_fin(const float* __restrict__ gamma,
                      const float* __restrict__ beta,
                      float* __restrict__ scl, float* __restrict__ bia, int N) {
    const int c = blockIdx.x;             // channel (storage index)
    const int t = threadIdx.x;            // 256 threads over 512 partials
    float s = g_ps[t * CH + c] + g_ps[(t + 256) * CH + c];
    float q = g_pq[t * CH + c] + g_pq[(t + 256) * CH + c];
    __shared__ float sh[256];
    __shared__ float shq[256];
    sh[t] = s; shq[t] = q;
    __syncthreads();
#pragma unroll
    for (int w = 128; w >= 1; w >>= 1) {
        if (t < w) { sh[t] += sh[t + w]; shq[t] += shq[t + w]; }
        __syncthreads();
    }
    if (t == 0) {
        float mu  = sh[0] / (float)N;
        float var = shq[0] / (float)N - mu * mu;
        if (var < 0.f) var = 0.f;
        float rs = rsqrtf(var + 1e-4f);
        int tc = c;
        if (MAP) {
            int cc = c >> 5, wi = c & 31, qn = wi >> 1, e = wi & 1;
            tc = cc * 32 + ipslot(qn) * 2 + e;
        }
        float sc = gamma[tc] * rs;
        scl[c] = sc;
        bia[c] = beta[tc] - mu * sc;
    }
}

// weight pack: transpose-to-[n][k], fp16, pslot layout, stage-linear planes
__global__ void k_wcvt(const float* __restrict__ W1, const float* __restrict__ W2,
                       const float* __restrict__ Wn) {
    const int T1 = KK * 2 * 128 * 16;
    const int T2 = T1 + KK * 4 * 128 * 16;
    const int T3 = T2 + 2 * 128 * 16;
    int idx = blockIdx.x * blockDim.x + threadIdx.x;
    if (idx >= T3) return;
    const float* src; uint32_t* dst; int n, p;
    if (idx < T1) {
        int k = idx / (2 * 128 * 16), r = idx % (2 * 128 * 16);
        int ch = r / (128 * 16), r2 = r % (128 * 16);
        n = r2 / 16; p = r2 % 16;
        src = W1 + (size_t)k * 64 * 128 + (size_t)(ch * 32 + 2 * p) * 128 + n;
        dst = g_W1p + (size_t)(k * 2 + ch) * 2560;
    } else if (idx < T2) {
        int i2 = idx - T1;
        int k = i2 / (4 * 128 * 16), r = i2 % (4 * 128 * 16);
        int ch = r / (128 * 16), r2 = r % (128 * 16);
        n = r2 / 16; p = r2 % 16;
        src = W2 + (size_t)k * 128 * 128 + (size_t)(ch * 32 + 2 * p) * 128 + n;
        dst = g_Wcat + (size_t)(2 + k * 4 + ch) * 2560;
    } else {
        int i2 = idx - T2;
        int ch = i2 / (128 * 16), r2 = i2 % (128 * 16);
        n = r2 / 16; p = r2 % 16;
        src = Wn + (size_t)(ch * 32 + 2 * p) * 128 + n;
        dst = g_Wcat + (size_t)ch * 2560;
    }
    float w0 = src[0], w1 = src[128];
    __half h0 = __float2half(w0);
    __half h1 = __float2half(w1);
    uint32_t hp = ((uint32_t)*(unsigned short*)&h1 << 16) |
                  (uint32_t)*(unsigned short*)&h0;
    dst[n * 20 + pslot(p)] = hp;
}

// ---------------- pure gather-GEMM conv kernel (round-13 verbatim) -----------
// MODE 1: mraw = sum_k a16[gidx_k] @ W1[k]                 (54 stages, fp16)
// MODE 2: out  = f16 @ Wnin + sum_k m16[gidx_k] @ W2[k]    (110 st, fp32)
// Block: 128 sites x 128 cols; 8 warps (4M x 2N); D in fp32 regs, write-once.
// Sources pre-permuted -> A-fill is a pure uint4 copy (2 LDG.128 + 2 STS.128).
// Triple-buffered smem, one barrier per stage.

#define BUFU32 (2560 + 2560)
#define SMEMB  (3 * BUFU32 * 4)

template <int MODE>
__global__ void __launch_bounds__(256, 2) k_conv(
    const uint32_t* __restrict__ src32, uint32_t* __restrict__ mid32,
    float* __restrict__ outp, int N) {

    constexpr int S = (MODE == 1) ? (KK * 2) : (2 + KK * 4);

    extern __shared__ char sm[];

    const int tid = threadIdx.x;
    const int wid = tid >> 5, lane = tid & 31;
    const int qr = lane >> 2, qc = lane & 3;
    const int wm = wid >> 1, wn = wid & 1;
    const int tile = blockIdx.x * 128;
    const int r = tid >> 1, h = tid & 1;
    const int site = tile + r;

    float acc[2][8][4];
#pragma unroll
    for (int a = 0; a < 2; a++)
#pragma unroll
        for (int b = 0; b < 8; b++)
#pragma unroll
            for (int c = 0; c < 4; c++) acc[a][b][c] = 0.f;

    auto rowOf = [&](int s) -> int {
        if (site >= N) return -1;
        if (MODE == 2 && s < 2) return site;                 // NiN dense
        int k = (MODE == 1) ? (s >> 1) : ((s - 2) >> 2);
        return g_gidx[(size_t)k * N + site];
    };

    uint4 rA2[2];
    uint4 rB[3];
    int   srA, srN;

    auto ldA = [&](int s, int sr) {
        const uint32_t* sp; int stride, c16;
        if (MODE == 2 && s < 2) { sp = g_f16;  stride = 32; c16 = s * 16; }
        else if (MODE == 1)     { sp = src32;  stride = 32; c16 = (s & 1) * 16; }
        else                    { sp = src32;  stride = 64; c16 = ((s - 2) & 3) * 16; }
        const uint4* rp = (const uint4*)(sp + (size_t)sr * stride + c16 + h * 8);
        if (sr >= 0) { rA2[0] = rp[0]; rA2[1] = rp[1]; }
    };
    auto ldB = [&](int s) {
        const uint32_t* bp = (MODE == 1) ? (g_W1p + (size_t)s * 2560)
                                         : (g_Wcat + (size_t)s * 2560);
        const uint4* wp = (const uint4*)bp;
#pragma unroll
        for (int j = 0; j < 3; j++) {
            int idx = tid + j * 256;
            if (idx < 640) rB[j] = wp[idx];
        }
    };
    auto stStage = [&](int buf) {
        uint32_t* Ab = (uint32_t*)(sm + buf * (BUFU32 * 4));
        uint32_t* Bb = Ab + 2560;
        {
            uint4* bd = (uint4*)Bb;
#pragma unroll
            for (int j = 0; j < 3; j++) {
                int idx = tid + j * 256;
                if (idx < 640) bd[idx] = rB[j];
            }
        }
        uint4* Aq = (uint4*)(Ab + r * 20 + h * 8);
        if (srA >= 0) { Aq[0] = rA2[0]; Aq[1] = rA2[1]; }
        else {
            uint4 z = make_uint4(0u, 0u, 0u, 0u);
            Aq[0] = z; Aq[1] = z;
        }
    };

    // ---- prologue
    srA = rowOf(0);
    ldA(0, srA);
    ldB(0);
    stStage(0);
    srN = (S > 1) ? rowOf(1) : -1;
    if (S > 1) { ldA(1, srN); ldB(1); }
    srA = srN;
    srN = (S > 2) ? rowOf(2) : -1;
    __syncthreads();

    // ---- main loop: one barrier per stage
    int bufMMA = 0;
#pragma unroll 3
    for (int s = 0; s < S; s++) {
        const uint32_t* Ab = (const uint32_t*)(sm + bufMMA * (BUFU32 * 4));
        const uint32_t* Bb = Ab + 2560;
#pragma unroll
        for (int g = 0; g < 2; g++) {
            uint2 a0[2], a1[2];
#pragma unroll
            for (int mt = 0; mt < 2; mt++) {
                int r0 = wm * 32 + mt * 16 + qr;
                a0[mt] = *(const uint2*)&Ab[r0 * 20 + g * 8 + qc * 2];
                a1[mt] = *(const uint2*)&Ab[(r0 + 8) * 20 + g * 8 + qc * 2];
            }
#pragma unroll
            for (int nt = 0; nt < 8; nt++) {
                int c0b = wn * 64 + nt * 8 + qr;
                uint2 bf = *(const uint2*)&Bb[c0b * 20 + g * 8 + qc * 2];
                mma_f16(acc[0][nt], a0[0], a1[0], bf);
                mma_f16(acc[1][nt], a0[1], a1[1], bf);
            }
        }

        int bufN = bufMMA + 1; if (bufN == 3) bufN = 0;
        if (s + 1 < S) stStage(bufN);
        if (s + 2 < S) {
            ldA(s + 2, srN);
            ldB(s + 2);
            srA = srN;
            if (s + 3 < S) srN = rowOf(s + 3);
        }
        __syncthreads();
        bufMMA = bufN;
    }

    // ---- epilogue
#pragma unroll
    for (int mt = 0; mt < 2; mt++) {
        int r0 = wm * 32 + mt * 16 + qr;
        int sA = tile + r0, sB = tile + r0 + 8;
#pragma unroll
        for (int nt = 0; nt < 8; nt++) {
            if (MODE == 1) {
                // fp16 permuted write: pair P at slot pslot(P&15) of chunk P>>4
                int P = wn * 32 + nt * 4 + qc;
                int pos = (P >> 4) * 16 + pslot(P & 15);
                if (sA < N)
                    mid32[(size_t)sA * 64 + pos] =
                        cvt2(acc[mt][nt][0], acc[mt][nt][1]);
                if (sB < N)
                    mid32[(size_t)sB * 64 + pos] =
                        cvt2(acc[mt][nt][2], acc[mt][nt][3]);
            } else {
                int col = wn * 64 + nt * 8 + qc * 2;
                if (sA < N)
                    *(float2*)(outp + (size_t)sA * BB + col) =
                        make_float2(acc[mt][nt][0], acc[mt][nt][1]);
                if (sB < N)
                    *(float2*)(outp + (size_t)sB * BB + col) =
                        make_float2(acc[mt][nt][2], acc[mt][nt][3]);
            }
        }
    }
}

// ---------------------------------------------------------------------------
extern "C" void kernel_launch(void* const* d_in, const int* in_sizes, int n_in,
                              void* d_out, int out_size) {
    const float* feat   = (const float*)d_in[0];
    const float* gamma1 = (const float*)d_in[1];
    const float* beta1  = (const float*)d_in[2];
    const float* W1     = (const float*)d_in[3];
    const float* gamma2 = (const float*)d_in[4];
    const float* beta2  = (const float*)d_in[5];
    const float* W2     = (const float*)d_in[6];
    const float* Wnin   = (const float*)d_in[7];
    const int*   nbr    = (const int*)d_in[8];
    const void*  mask   = d_in[9];
    float*       out    = (float*)d_out;

    const int N = in_sizes[0] / AA;

    float *p_s1, *p_b1, *p_s2, *p_b2;
    uint32_t *p_a16, *p_m16, *p_mraw;
    cudaGetSymbolAddress((void**)&p_s1,   g_s1);
    cudaGetSymbolAddress((void**)&p_b1,   g_b1);
    cudaGetSymbolAddress((void**)&p_s2,   g_s2);
    cudaGetSymbolAddress((void**)&p_b2,   g_b2);
    cudaGetSymbolAddress((void**)&p_a16,  g_a16);
    cudaGetSymbolAddress((void**)&p_m16,  g_m16);
    cudaGetSymbolAddress((void**)&p_mraw, g_mraw);

    cudaFuncSetAttribute(k_conv<1>,
                         cudaFuncAttributeMaxDynamicSharedMemorySize, SMEMB);
    cudaFuncSetAttribute(k_conv<2>,
                         cudaFuncAttributeMaxDynamicSharedMemorySize, SMEMB);

    const int gtiles = (N + 127) / 128;
    const int wtot   = KK * 2 * 128 * 16 + KK * 4 * 128 * 16 + 2 * 128 * 16;
    const int n16    = N * 16;    // float4s in feat
    const int n32    = N * 32;    // uint2s in mid

    // prep: gather index (with fused mask detect), weight pack
    k_gidx<<<(N + 255) / 256, 256>>>(nbr, mask, N);
    k_wcvt<<<(wtot + 255) / 256, 256>>>(W1, W2, Wnin);

    // BN1: stats on fp32 feat -> parallel folded affine -> fused apply
    k_stats<AA, 4><<<PB, dim3(AA, 4)>>>(feat, N);
    k_fin<AA, false><<<AA, 256>>>(gamma1, beta1, p_s1, p_b1, N);
    k_bn1<<<(n16 + 255) / 256, 256>>>(feat, p_s1, p_b1, n16);

    // conv1 -> g_mraw (fp16, permuted)
    k_conv<1><<<gtiles, 256, SMEMB>>>(p_a16, p_mraw, nullptr, N);

    // BN2: stats on fp16 mid -> parallel folded affine (gamma mapped) -> apply
    k_stats16<4><<<PB, dim3(64, 4)>>>(N);
    k_fin<BB, true><<<BB, 256>>>(gamma2, beta2, p_s2, p_b2, N);
    k_bn2<<<(n32 + 255) / 256, 256>>>(p_s2, p_b2, n32);

    // conv2 (NiN fused as 2 leading dense stages) -> out (write-once fp32)
    k_conv<2><<<gtiles, 256, SMEMB>>>(p_m16, nullptr, out, N);
}

// round 16
// speedup vs baseline: 1.6483x; 1.1118x over previous
#include <cuda_runtime.h>
#include <cuda_fp16.h>
#include <cstdint>

// ---------------------------------------------------------------------------
// ResidualBlock: y = feat@Wnin + subconv(bnrelu2(subconv(bnrelu1(feat),W1)),W2)
// N=100000, A=64, B=128, K=27. fp32 in/out.
// Engine: mma.sync m16n8k16 fp16 (HMMA), single pass, fp32 accum.
// Round-16: FAT 64-channel stages (conv1 27, conv2 55) at 2 CTA/SM.
//   A: register-staged 1-ahead, double-buffered smem (plane stride 2564).
//   B: cp.async 2-ahead into a 3-slot ring (linear 20KB copies, no regs).
//   One barrier + one cp.async group per stage.
// Mask semantics: masked-off rows contribute TRUE zeros.
// ---------------------------------------------------------------------------

#define KK   27
#define AA   64
#define BB   128
#define NMAX 100000
#define PB   512

// ---------------- static device scratch ------------------------------------
// fp16 activation buffers as u32 (=channel-pair) arrays, fragment-slot order
__device__ __align__(16) uint32_t g_f16[(size_t)NMAX * 32];   // raw feat
__device__ __align__(16) uint32_t g_a16[(size_t)NMAX * 32];   // bnrelu1(feat)
__device__ __align__(16) uint32_t g_mraw[(size_t)NMAX * 64];  // conv1 out
__device__ __align__(16) uint32_t g_m16[(size_t)NMAX * 64];   // bnrelu2(mid)
__device__ int   g_gidx[KK * NMAX];                           // gather idx/-1
__device__ float g_ps[PB * BB], g_pq[PB * BB];
__device__ float g_s1[AA], g_b1[AA], g_s2[BB], g_b2[BB];
// packed fp16 weight planes (2560 u32 each, n*20 + pslot(p)); stage-linear.
// Fat stage (64 ch) = 2 consecutive planes = 5120 u32.
__device__ __align__(16) uint32_t g_W1p[KK * 2 * 2560];
__device__ __align__(16) uint32_t g_Wcat[(2 + KK * 4) * 2560]; // [Wnin|W2]

// pair p (0..15) -> interleaved slot so fragment reg pairs are adjacent
__host__ __device__ __forceinline__ int pslot(int p) {
    return (p >> 3) * 8 + ((p & 3) * 2) + ((p & 7) >> 2);
}
// inverse of pslot
__host__ __device__ __forceinline__ int ipslot(int q) {
    int qq = q & 7, base = q & 8;
    return base + ((qq & 1) ? 4 + (qq >> 1) : (qq >> 1));
}

// pack two fp32 -> f16x2 (low half = first arg)
__device__ __forceinline__ uint32_t cvt2(float lo, float hi) {
    uint32_t r;
    asm("cvt.rn.f16x2.f32 %0, %1, %2;" : "=r"(r) : "f"(hi), "f"(lo));
    return r;
}

// mma.sync m16n8k16 f16: a={a0.x,a1.x,a0.y,a1.y}, b={b.x,b.y}, d += a@b
__device__ __forceinline__ void mma_f16(float* d, uint2 a0, uint2 a1, uint2 b) {
    asm volatile(
        "mma.sync.aligned.m16n8k16.row.col.f32.f16.f16.f32 "
        "{%0,%1,%2,%3}, {%4,%5,%6,%7}, {%8,%9}, {%0,%1,%2,%3};"
        : "+f"(d[0]), "+f"(d[1]), "+f"(d[2]), "+f"(d[3])
        : "r"(a0.x), "r"(a1.x), "r"(a0.y), "r"(a1.y), "r"(b.x), "r"(b.y));
}

__device__ __forceinline__ uint32_t smem_u32(const void* p) {
    uint32_t a;
    asm("{ .reg .u64 t; cvta.to.shared.u64 t, %1; cvt.u32.u64 %0, t; }"
        : "=r"(a) : "l"(p));
    return a;
}

// ---------------- small kernels --------------------------------------------
// gather index precompute with per-block mask-dtype detection
__global__ void k_gidx(const int* __restrict__ nbr,
                       const void* __restrict__ mp, int N) {
    __shared__ int s_u8;
    int t = threadIdx.x;
    int i = blockIdx.x * 256 + t;
    int probe = (i < N) ? i : (N - 1);
    int ok = (((const unsigned char*)mp)[(size_t)probe * KK + KK / 2] != 0);
    int all = __syncthreads_and(ok);
    if (t == 0) s_u8 = all;
    __syncthreads();
    if (i >= N) return;
    const bool u8 = (s_u8 != 0);
    const unsigned char* m8  = (const unsigned char*)mp;
    const int*           m32 = (const int*)mp;
#pragma unroll
    for (int k = 0; k < KK; k++) {
        bool m = u8 ? (m8[(size_t)i * KK + k] != 0)
                    : (m32[(size_t)i * KK + k] != 0);
        g_gidx[k * N + i] = m ? nbr[(size_t)i * KK + k] : -1;
    }
}

// BN1 apply + raw convert, fused: feat fp32 -> g_a16 (bn) + g_f16 (raw),
// both fp16 PERMUTED (pair p at pslot(p) within each 16-u32 chunk).
__global__ void k_bn1(const float* __restrict__ x,
                      const float* __restrict__ scl,
                      const float* __restrict__ bia, int n16) {
    int i = blockIdx.x * blockDim.x + threadIdx.x;
    if (i >= n16) return;                 // i indexes float4 over N*16
    float4 v = ((const float4*)x)[i];
    int row = i >> 4, t = i & 15;
    int c = t * 4;                        // true channel base
    int cc = t >> 3, p0 = (2 * t) & 15;
    int base = row * 32 + cc * 16;
    int pos0 = base + pslot(p0), pos1 = base + pslot(p0 + 1);
    g_f16[pos0] = cvt2(v.x, v.y);
    g_f16[pos1] = cvt2(v.z, v.w);
    float4 w;
    w.x = fmaxf(fmaf(v.x, scl[c],     bia[c]),     0.f);
    w.y = fmaxf(fmaf(v.y, scl[c + 1], bia[c + 1]), 0.f);
    w.z = fmaxf(fmaf(v.z, scl[c + 2], bia[c + 2]), 0.f);
    w.w = fmaxf(fmaf(v.w, scl[c + 3], bia[c + 3]), 0.f);
    g_a16[pos0] = cvt2(w.x, w.y);
    g_a16[pos1] = cvt2(w.z, w.w);
}

// BN2 apply: g_mraw (fp16 permuted) -> g_m16; positions identity, scale
// arrays are STORAGE-indexed (fin2 does the gamma/beta index mapping).
__global__ void k_bn2(const float* __restrict__ scl,
                      const float* __restrict__ bia, int n32) {
    int i = blockIdx.x * blockDim.x + threadIdx.x;
    if (i >= n32) return;                 // i indexes uint2 over N*32
    uint2 x = ((const uint2*)g_mraw)[i];
    int c = (i & 31) * 4;                 // storage channel base
    float2 f0 = __half22float2(*(const __half2*)&x.x);
    float2 f1 = __half22float2(*(const __half2*)&x.y);
    f0.x = fmaxf(fmaf(f0.x, scl[c],     bia[c]),     0.f);
    f0.y = fmaxf(fmaf(f0.y, scl[c + 1], bia[c + 1]), 0.f);
    f1.x = fmaxf(fmaf(f1.x, scl[c + 2], bia[c + 2]), 0.f);
    f1.y = fmaxf(fmaf(f1.y, scl[c + 3], bia[c + 3]), 0.f);
    uint2 r;
    r.x = cvt2(f0.x, f0.y);
    r.y = cvt2(f1.x, f1.y);
    ((uint2*)g_m16)[i] = r;
}

// fp32 stats (BN1): block (CH, RG)
template <int CH, int RG>
__global__ void k_stats(const float* __restrict__ x, int N) {
    int c = threadIdx.x, r = threadIdx.y;
    float s = 0.f, q = 0.f;
    for (int i = blockIdx.x * RG + r; i < N; i += gridDim.x * RG) {
        float v = x[(size_t)i * CH + c];
        s += v; q += v * v;
    }
    __shared__ float sh[RG][CH];
    __shared__ float shq[RG][CH];
    sh[r][c] = s; shq[r][c] = q;
    __syncthreads();
    if (r == 0) {
#pragma unroll
        for (int j = 1; j < RG; j++) { s += sh[j][c]; q += shq[j][c]; }
        g_ps[blockIdx.x * CH + c] = s;
        g_pq[blockIdx.x * CH + c] = q;
    }
}

// fp16 stats (BN2) over g_mraw: block (64 positions, RG); 2 channels/thread
template <int RG>
__global__ void k_stats16(int N) {
    int pos = threadIdx.x, r = threadIdx.y;
    float sl = 0.f, ql = 0.f, sh2 = 0.f, qh = 0.f;
    for (int i = blockIdx.x * RG + r; i < N; i += gridDim.x * RG) {
        uint32_t w = g_mraw[(size_t)i * 64 + pos];
        float2 f = __half22float2(*(const __half2*)&w);
        sl += f.x; ql += f.x * f.x;
        sh2 += f.y; qh += f.y * f.y;
    }
    __shared__ float sa[RG][128];
    __shared__ float sb[RG][128];
    sa[r][pos * 2] = sl;  sa[r][pos * 2 + 1] = sh2;
    sb[r][pos * 2] = ql;  sb[r][pos * 2 + 1] = qh;
    __syncthreads();
    if (r == 0) {
        float s0 = sa[0][pos * 2], s1 = sa[0][pos * 2 + 1];
        float q0 = sb[0][pos * 2], q1 = sb[0][pos * 2 + 1];
#pragma unroll
        for (int j = 1; j < RG; j++) {
            s0 += sa[j][pos * 2]; s1 += sa[j][pos * 2 + 1];
            q0 += sb[j][pos * 2]; q1 += sb[j][pos * 2 + 1];
        }
        g_ps[blockIdx.x * 128 + pos * 2]     = s0;
        g_ps[blockIdx.x * 128 + pos * 2 + 1] = s1;
        g_pq[blockIdx.x * 128 + pos * 2]     = q0;
        g_pq[blockIdx.x * 128 + pos * 2 + 1] = q1;
    }
}

// PARALLEL finisher: ONE BLOCK PER CHANNEL (grid = CH, block = 256).
template <int CH, bool MAP>
__global__ void k_fin(const float* __restrict__ gamma,
                      const float* __restrict__ beta,
                      float* __restrict__ scl, float* __restrict__ bia, int N) {
    const int c = blockIdx.x;
    const int t = threadIdx.x;
    float s = g_ps[t * CH + c] + g_ps[(t + 256) * CH + c];
    float q = g_pq[t * CH + c] + g_pq[(t + 256) * CH + c];
    __shared__ float sh[256];
    __shared__ float shq[256];
    sh[t] = s; shq[t] = q;
    __syncthreads();
#pragma unroll
    for (int w = 128; w >= 1; w >>= 1) {
        if (t < w) { sh[t] += sh[t + w]; shq[t] += shq[t + w]; }
        __syncthreads();
    }
    if (t == 0) {
        float mu  = sh[0] / (float)N;
        float var = shq[0] / (float)N - mu * mu;
        if (var < 0.f) var = 0.f;
        float rs = rsqrtf(var + 1e-4f);
        int tc = c;
        if (MAP) {
            int cc = c >> 5, wi = c & 31, qn = wi >> 1, e = wi & 1;
            tc = cc * 32 + ipslot(qn) * 2 + e;
        }
        float sc = gamma[tc] * rs;
        scl[c] = sc;
        bia[c] = beta[tc] - mu * sc;
    }
}

// weight pack: transpose-to-[n][k], fp16, pslot layout, stage-linear planes
__global__ void k_wcvt(const float* __restrict__ W1, const float* __restrict__ W2,
                       const float* __restrict__ Wn) {
    const int T1 = KK * 2 * 128 * 16;
    const int T2 = T1 + KK * 4 * 128 * 16;
    const int T3 = T2 + 2 * 128 * 16;
    int idx = blockIdx.x * blockDim.x + threadIdx.x;
    if (idx >= T3) return;
    const float* src; uint32_t* dst; int n, p;
    if (idx < T1) {
        int k = idx / (2 * 128 * 16), r = idx % (2 * 128 * 16);
        int ch = r / (128 * 16), r2 = r % (128 * 16);
        n = r2 / 16; p = r2 % 16;
        src = W1 + (size_t)k * 64 * 128 + (size_t)(ch * 32 + 2 * p) * 128 + n;
        dst = g_W1p + (size_t)(k * 2 + ch) * 2560;
    } else if (idx < T2) {
        int i2 = idx - T1;
        int k = i2 / (4 * 128 * 16), r = i2 % (4 * 128 * 16);
        int ch = r / (128 * 16), r2 = r % (128 * 16);
        n = r2 / 16; p = r2 % 16;
        src = W2 + (size_t)k * 128 * 128 + (size_t)(ch * 32 + 2 * p) * 128 + n;
        dst = g_Wcat + (size_t)(2 + k * 4 + ch) * 2560;
    } else {
        int i2 = idx - T2;
        int ch = i2 / (128 * 16), r2 = i2 % (128 * 16);
        n = r2 / 16; p = r2 % 16;
        src = Wn + (size_t)(ch * 32 + 2 * p) * 128 + n;
        dst = g_Wcat + (size_t)ch * 2560;
    }
    float w0 = src[0], w1 = src[128];
    __half h0 = __float2half(w0);
    __half h1 = __float2half(w1);
    uint32_t hp = ((uint32_t)*(unsigned short*)&h1 << 16) |
                  (uint32_t)*(unsigned short*)&h0;
    dst[n * 20 + pslot(p)] = hp;
}

// ---------------- fat-stage gather-GEMM conv kernel --------------------------
// MODE 1: mraw = sum_k a16[gidx_k] @ W1[k]                 (27 stages, fp16)
// MODE 2: out  = f16 @ Wnin + sum_k m16[gidx_k] @ W2[k]    (55 stages, fp32)
// Stage = 64 channels (2 weight planes). A double-buffered (plane stride
// 2564), B in a 3-slot cp.async ring. One barrier + one group per stage.

#define APL   2564                        // A plane stride (u32), padded
#define ABUF  (2 * APL)                   // A u32 per buffer (2 planes)
#define ABYTES (2 * ABUF * 4)             // both A buffers
#define BSLOT 5120                        // B u32 per stage (2 planes)
#define SMEMB (ABYTES + 3 * BSLOT * 4)    // 41024 + 61440 = 102464 bytes

template <int MODE>
__global__ void __launch_bounds__(256, 2) k_conv(
    const uint32_t* __restrict__ src32, uint32_t* __restrict__ mid32,
    float* __restrict__ outp, int N) {

    constexpr int S = (MODE == 1) ? KK : (1 + KK * 2);

    extern __shared__ char sm[];
    const uint32_t smb = smem_u32(sm);
    const uint32_t bbase = smb + (uint32_t)ABYTES;

    const int tid = threadIdx.x;
    const int wid = tid >> 5, lane = tid & 31;
    const int qr = lane >> 2, qc = lane & 3;
    const int wm = wid >> 1, wn = wid & 1;
    const int tile = blockIdx.x * 128;
    const int r = tid >> 1, h = tid & 1;
    const int site = tile + r;

    float acc[2][8][4];
#pragma unroll
    for (int a = 0; a < 2; a++)
#pragma unroll
        for (int b = 0; b < 8; b++)
#pragma unroll
            for (int c = 0; c < 4; c++) acc[a][b][c] = 0.f;

    auto rowOf = [&](int s) -> int {
        if (site >= N) return -1;
        if (MODE == 2) {
            if (s < 1) return site;                          // NiN dense
            return g_gidx[(size_t)((s - 1) >> 1) * N + site];
        }
        return g_gidx[(size_t)s * N + site];
    };

    uint4 rA2[4];           // staged A: 16 u32 = this thread's half-row plane
    int   srA, srN;

    auto ldA = [&](int s, int sr) {
        const uint32_t* sp; int stride, c16;
        if (MODE == 1)          { sp = src32; stride = 32; c16 = h * 16; }
        else if (s < 1)         { sp = g_f16; stride = 32; c16 = h * 16; }
        else                    { sp = src32; stride = 64;
                                  c16 = ((s - 1) & 1) * 32 + h * 16; }
        const uint4* rp = (const uint4*)(sp + (size_t)sr * stride + c16);
        if (sr >= 0) {
#pragma unroll
            for (int j = 0; j < 4; j++) rA2[j] = rp[j];
        }
    };
    auto stA = [&](int buf) {
        uint32_t* Ab = (uint32_t*)sm + buf * ABUF + h * APL + r * 20;
        if (srA >= 0) {
#pragma unroll
            for (int j = 0; j < 4; j++) *(uint4*)(Ab + j * 4) = rA2[j];
        } else {
            uint4 z = make_uint4(0u, 0u, 0u, 0u);
#pragma unroll
            for (int j = 0; j < 4; j++) *(uint4*)(Ab + j * 4) = z;
        }
    };
    auto cpB = [&](int s, int slot) {
        const uint32_t* bp = (MODE == 1) ? (g_W1p + (size_t)s * BSLOT)
                                         : (g_Wcat + (size_t)s * BSLOT);
        uint32_t dst = bbase + (uint32_t)slot * (BSLOT * 4) + (uint32_t)tid * 16;
        const char* srcp = (const char*)bp + (size_t)tid * 16;
#pragma unroll
        for (int j = 0; j < 5; j++)
            asm volatile("cp.async.cg.shared.global [%0], [%1], 16;"
                         :: "r"(dst + (uint32_t)j * 4096u),
                            "l"(srcp + (size_t)j * 4096) : "memory");
    };

    // ---- prologue: B(0), B(1) in flight; A(0) stored; A(1) staged ---------
    cpB(0, 0);
    asm volatile("cp.async.commit_group;" ::: "memory");
    if (S > 1) cpB(1, 1);
    asm volatile("cp.async.commit_group;" ::: "memory");
    srA = rowOf(0);
    ldA(0, srA);
    stA(0);
    srN = (S > 1) ? rowOf(1) : -1;
    if (S > 1) { ldA(1, srN); }
    srA = srN;
    srN = (S > 2) ? rowOf(2) : -1;
    asm volatile("cp.async.wait_group 1;" ::: "memory");   // B(0) landed
    __syncthreads();

    // ---- main loop: one barrier + one group per stage ---------------------
    int bsl = 0;                      // s % 3
    for (int s = 0; s < S; s++) {
        const uint32_t* Ab = (const uint32_t*)sm + (s & 1) * ABUF;
        const uint32_t* Bb = (const uint32_t*)(sm + ABYTES) + bsl * BSLOT;

        // MMA: 2 chunk planes x 2 k16 steps x (2M x 8N)
#pragma unroll
        for (int g = 0; g < 4; g++) {
            const uint32_t* Ap = Ab + (g >> 1) * APL + (g & 1) * 8;
            const uint32_t* Bp = Bb + (g >> 1) * 2560 + (g & 1) * 8;
            uint2 a0[2], a1[2];
#pragma unroll
            for (int mt = 0; mt < 2; mt++) {
                int r0 = wm * 32 + mt * 16 + qr;
                a0[mt] = *(const uint2*)&Ap[r0 * 20 + qc * 2];
                a1[mt] = *(const uint2*)&Ap[(r0 + 8) * 20 + qc * 2];
            }
#pragma unroll
            for (int nt = 0; nt < 8; nt++) {
                int c0b = wn * 64 + nt * 8 + qr;
                uint2 bf = *(const uint2*)&Bp[c0b * 20 + qc * 2];
                mma_f16(acc[0][nt], a0[0], a1[0], bf);
                mma_f16(acc[1][nt], a0[1], a1[1], bf);
            }
        }

        // STS A(s+1) from staged regs
        if (s + 1 < S) stA((s + 1) & 1);
        // cp.async B(s+2) into ring slot (s+2)%3
        if (s + 2 < S) {
            int sl2 = bsl + 2; if (sl2 >= 3) sl2 -= 3;
            cpB(s + 2, sl2);
        }
        asm volatile("cp.async.commit_group;" ::: "memory");
        // LDG A(s+2) -> staged regs
        if (s + 2 < S) {
            ldA(s + 2, srN);
            srA = srN;
            if (s + 3 < S) srN = rowOf(s + 3);
        }
        asm volatile("cp.async.wait_group 1;" ::: "memory"); // B(s+1) landed
        __syncthreads();
        if (++bsl == 3) bsl = 0;
    }

    // ---- epilogue ---------------------------------------------------------
#pragma unroll
    for (int mt = 0; mt < 2; mt++) {
        int r0 = wm * 32 + mt * 16 + qr;
        int sA = tile + r0, sB = tile + r0 + 8;
#pragma unroll
        for (int nt = 0; nt < 8; nt++) {
            if (MODE == 1) {
                int P = wn * 32 + nt * 4 + qc;
                int pos = (P >> 4) * 16 + pslot(P & 15);
                if (sA < N)
                    mid32[(size_t)sA * 64 + pos] =
                        cvt2(acc[mt][nt][0], acc[mt][nt][1]);
                if (sB < N)
                    mid32[(size_t)sB * 64 + pos] =
                        cvt2(acc[mt][nt][2], acc[mt][nt][3]);
            } else {
                int col = wn * 64 + nt * 8 + qc * 2;
                if (sA < N)
                    *(float2*)(outp + (size_t)sA * BB + col) =
                        make_float2(acc[mt][nt][0], acc[mt][nt][1]);
                if (sB < N)
                    *(float2*)(outp + (size_t)sB * BB + col) =
                        make_float2(acc[mt][nt][2], acc[mt][nt][3]);
            }
        }
    }
}

// ---------------------------------------------------------------------------
extern "C" void kernel_launch(void* const* d_in, const int* in_sizes, int n_in,
                              void* d_out, int out_size) {
    const float* feat   = (const float*)d_in[0];
    const float* gamma1 = (const float*)d_in[1];
    const float* beta1  = (const float*)d_in[2];
    const float* W1     = (const float*)d_in[3];
    const float* gamma2 = (const float*)d_in[4];
    const float* beta2  = (const float*)d_in[5];
    const float* W2     = (const float*)d_in[6];
    const float* Wnin   = (const float*)d_in[7];
    const int*   nbr    = (const int*)d_in[8];
    const void*  mask   = d_in[9];
    float*       out    = (float*)d_out;

    const int N = in_sizes[0] / AA;

    float *p_s1, *p_b1, *p_s2, *p_b2;
    uint32_t *p_a16, *p_m16, *p_mraw;
    cudaGetSymbolAddress((void**)&p_s1,   g_s1);
    cudaGetSymbolAddress((void**)&p_b1,   g_b1);
    cudaGetSymbolAddress((void**)&p_s2,   g_s2);
    cudaGetSymbolAddress((void**)&p_b2,   g_b2);
    cudaGetSymbolAddress((void**)&p_a16,  g_a16);
    cudaGetSymbolAddress((void**)&p_m16,  g_m16);
    cudaGetSymbolAddress((void**)&p_mraw, g_mraw);

    cudaFuncSetAttribute(k_conv<1>,
                         cudaFuncAttributeMaxDynamicSharedMemorySize, SMEMB);
    cudaFuncSetAttribute(k_conv<2>,
                         cudaFuncAttributeMaxDynamicSharedMemorySize, SMEMB);

    const int gtiles = (N + 127) / 128;
    const int wtot   = KK * 2 * 128 * 16 + KK * 4 * 128 * 16 + 2 * 128 * 16;
    const int n16    = N * 16;    // float4s in feat
    const int n32    = N * 32;    // uint2s in mid

    // prep: gather index (with fused mask detect), weight pack
    k_gidx<<<(N + 255) / 256, 256>>>(nbr, mask, N);
    k_wcvt<<<(wtot + 255) / 256, 256>>>(W1, W2, Wnin);

    // BN1: stats on fp32 feat -> parallel folded affine -> fused apply
    k_stats<AA, 4><<<PB, dim3(AA, 4)>>>(feat, N);
    k_fin<AA, false><<<AA, 256>>>(gamma1, beta1, p_s1, p_b1, N);
    k_bn1<<<(n16 + 255) / 256, 256>>>(feat, p_s1, p_b1, n16);

    // conv1 (27 fat stages) -> g_mraw (fp16, permuted)
    k_conv<1><<<gtiles, 256, SMEMB>>>(p_a16, p_mraw, nullptr, N);

    // BN2: stats on fp16 mid -> parallel folded affine (gamma mapped) -> apply
    k_stats16<4><<<PB, dim3(64, 4)>>>(N);
    k_fin<BB, true><<<BB, 256>>>(gamma2, beta2, p_s2, p_b2, N);
    k_bn2<<<(n32 + 255) / 256, 256>>>(p_s2, p_b2, n32);

    // conv2 (1 NiN + 54 fat stages) -> out (write-once fp32)
    k_conv<2><<<gtiles, 256, SMEMB>>>(p_m16, nullptr, out, N);
}

// round 17
// speedup vs baseline: 1.9094x; 1.1584x over previous
#include <cuda_runtime.h>
#include <cuda_fp16.h>
#include <cstdint>

// ---------------------------------------------------------------------------
// ResidualBlock: y = feat@Wnin + subconv(bnrelu2(subconv(bnrelu1(feat),W1)),W2)
// N=100000, A=64, B=128, K=27. fp32 in/out.
// Engine: mma.sync m16n8k16 fp16 (HMMA), single pass, fp32 accum.
// Round-17: CONFLICT-FREE smem (stride 24 u32: qr*24 mod 32 = {0,24,16,8} ->
// every 16-lane LDS.64 phase tiles all 32 banks exactly once; A h-planes at
// +3076 for a 4-bank interleave on stores). B ring 3->2 slots to keep
// 2 CTA/SM. Fat 64-channel stages, one barrier per stage.
// Mask semantics: masked-off rows contribute TRUE zeros.
// ---------------------------------------------------------------------------

#define KK   27
#define AA   64
#define BB   128
#define NMAX 100000
#define PB   512

// ---------------- static device scratch ------------------------------------
// fp16 activation buffers as u32 (=channel-pair) arrays, fragment-slot order
__device__ __align__(16) uint32_t g_f16[(size_t)NMAX * 32];   // raw feat
__device__ __align__(16) uint32_t g_a16[(size_t)NMAX * 32];   // bnrelu1(feat)
__device__ __align__(16) uint32_t g_mraw[(size_t)NMAX * 64];  // conv1 out
__device__ __align__(16) uint32_t g_m16[(size_t)NMAX * 64];   // bnrelu2(mid)
__device__ int   g_gidx[KK * NMAX];                           // gather idx/-1
__device__ float g_ps[PB * BB], g_pq[PB * BB];
__device__ float g_s1[AA], g_b1[AA], g_s2[BB], g_b2[BB];
// packed fp16 weight planes, stride-24 padded: plane = 3072 u32
// (n*24 + pslot(p), slots 16..23 pad). Stage-linear; fat stage = 2 planes.
__device__ __align__(16) uint32_t g_W1p[KK * 2 * 3072];
__device__ __align__(16) uint32_t g_Wcat[(2 + KK * 4) * 3072]; // [Wnin|W2]

// pair p (0..15) -> interleaved slot so fragment reg pairs are adjacent
__host__ __device__ __forceinline__ int pslot(int p) {
    return (p >> 3) * 8 + ((p & 3) * 2) + ((p & 7) >> 2);
}
// inverse of pslot
__host__ __device__ __forceinline__ int ipslot(int q) {
    int qq = q & 7, base = q & 8;
    return base + ((qq & 1) ? 4 + (qq >> 1) : (qq >> 1));
}

// pack two fp32 -> f16x2 (low half = first arg)
__device__ __forceinline__ uint32_t cvt2(float lo, float hi) {
    uint32_t r;
    asm("cvt.rn.f16x2.f32 %0, %1, %2;" : "=r"(r) : "f"(hi), "f"(lo));
    return r;
}

// mma.sync m16n8k16 f16: a={a0.x,a1.x,a0.y,a1.y}, b={b.x,b.y}, d += a@b
__device__ __forceinline__ void mma_f16(float* d, uint2 a0, uint2 a1, uint2 b) {
    asm volatile(
        "mma.sync.aligned.m16n8k16.row.col.f32.f16.f16.f32 "
        "{%0,%1,%2,%3}, {%4,%5,%6,%7}, {%8,%9}, {%0,%1,%2,%3};"
        : "+f"(d[0]), "+f"(d[1]), "+f"(d[2]), "+f"(d[3])
        : "r"(a0.x), "r"(a1.x), "r"(a0.y), "r"(a1.y), "r"(b.x), "r"(b.y));
}

__device__ __forceinline__ uint32_t smem_u32(const void* p) {
    uint32_t a;
    asm("{ .reg .u64 t; cvta.to.shared.u64 t, %1; cvt.u32.u64 %0, t; }"
        : "=r"(a) : "l"(p));
    return a;
}

// ---------------- small kernels --------------------------------------------
// gather index precompute with per-block mask-dtype detection
__global__ void k_gidx(const int* __restrict__ nbr,
                       const void* __restrict__ mp, int N) {
    __shared__ int s_u8;
    int t = threadIdx.x;
    int i = blockIdx.x * 256 + t;
    int probe = (i < N) ? i : (N - 1);
    int ok = (((const unsigned char*)mp)[(size_t)probe * KK + KK / 2] != 0);
    int all = __syncthreads_and(ok);
    if (t == 0) s_u8 = all;
    __syncthreads();
    if (i >= N) return;
    const bool u8 = (s_u8 != 0);
    const unsigned char* m8  = (const unsigned char*)mp;
    const int*           m32 = (const int*)mp;
#pragma unroll
    for (int k = 0; k < KK; k++) {
        bool m = u8 ? (m8[(size_t)i * KK + k] != 0)
                    : (m32[(size_t)i * KK + k] != 0);
        g_gidx[k * N + i] = m ? nbr[(size_t)i * KK + k] : -1;
    }
}

// BN1 apply + raw convert, fused: feat fp32 -> g_a16 (bn) + g_f16 (raw),
// both fp16 PERMUTED (pair p at pslot(p) within each 16-u32 chunk).
__global__ void k_bn1(const float* __restrict__ x,
                      const float* __restrict__ scl,
                      const float* __restrict__ bia, int n16) {
    int i = blockIdx.x * blockDim.x + threadIdx.x;
    if (i >= n16) return;                 // i indexes float4 over N*16
    float4 v = ((const float4*)x)[i];
    int row = i >> 4, t = i & 15;
    int c = t * 4;                        // true channel base
    int cc = t >> 3, p0 = (2 * t) & 15;
    int base = row * 32 + cc * 16;
    int pos0 = base + pslot(p0), pos1 = base + pslot(p0 + 1);
    g_f16[pos0] = cvt2(v.x, v.y);
    g_f16[pos1] = cvt2(v.z, v.w);
    float4 w;
    w.x = fmaxf(fmaf(v.x, scl[c],     bia[c]),     0.f);
    w.y = fmaxf(fmaf(v.y, scl[c + 1], bia[c + 1]), 0.f);
    w.z = fmaxf(fmaf(v.z, scl[c + 2], bia[c + 2]), 0.f);
    w.w = fmaxf(fmaf(v.w, scl[c + 3], bia[c + 3]), 0.f);
    g_a16[pos0] = cvt2(w.x, w.y);
    g_a16[pos1] = cvt2(w.z, w.w);
}

// BN2 apply: g_mraw (fp16 permuted) -> g_m16; positions identity, scale
// arrays are STORAGE-indexed (fin2 does the gamma/beta index mapping).
__global__ void k_bn2(const float* __restrict__ scl,
                      const float* __restrict__ bia, int n32) {
    int i = blockIdx.x * blockDim.x + threadIdx.x;
    if (i >= n32) return;                 // i indexes uint2 over N*32
    uint2 x = ((const uint2*)g_mraw)[i];
    int c = (i & 31) * 4;                 // storage channel base
    float2 f0 = __half22float2(*(const __half2*)&x.x);
    float2 f1 = __half22float2(*(const __half2*)&x.y);
    f0.x = fmaxf(fmaf(f0.x, scl[c],     bia[c]),     0.f);
    f0.y = fmaxf(fmaf(f0.y, scl[c + 1], bia[c + 1]), 0.f);
    f1.x = fmaxf(fmaf(f1.x, scl[c + 2], bia[c + 2]), 0.f);
    f1.y = fmaxf(fmaf(f1.y, scl[c + 3], bia[c + 3]), 0.f);
    uint2 r;
    r.x = cvt2(f0.x, f0.y);
    r.y = cvt2(f1.x, f1.y);
    ((uint2*)g_m16)[i] = r;
}

// fp32 stats (BN1): block (CH, RG)
template <int CH, int RG>
__global__ void k_stats(const float* __restrict__ x, int N) {
    int c = threadIdx.x, r = threadIdx.y;
    float s = 0.f, q = 0.f;
    for (int i = blockIdx.x * RG + r; i < N; i += gridDim.x * RG) {
        float v = x[(size_t)i * CH + c];
        s += v; q += v * v;
    }
    __shared__ float sh[RG][CH];
    __shared__ float shq[RG][CH];
    sh[r][c] = s; shq[r][c] = q;
    __syncthreads();
    if (r == 0) {
#pragma unroll
        for (int j = 1; j < RG; j++) { s += sh[j][c]; q += shq[j][c]; }
        g_ps[blockIdx.x * CH + c] = s;
        g_pq[blockIdx.x * CH + c] = q;
    }
}

// fp16 stats (BN2) over g_mraw: block (64 positions, RG); 2 channels/thread
template <int RG>
__global__ void k_stats16(int N) {
    int pos = threadIdx.x, r = threadIdx.y;
    float sl = 0.f, ql = 0.f, sh2 = 0.f, qh = 0.f;
    for (int i = blockIdx.x * RG + r; i < N; i += gridDim.x * RG) {
        uint32_t w = g_mraw[(size_t)i * 64 + pos];
        float2 f = __half22float2(*(const __half2*)&w);
        sl += f.x; ql += f.x * f.x;
        sh2 += f.y; qh += f.y * f.y;
    }
    __shared__ float sa[RG][128];
    __shared__ float sb[RG][128];
    sa[r][pos * 2] = sl;  sa[r][pos * 2 + 1] = sh2;
    sb[r][pos * 2] = ql;  sb[r][pos * 2 + 1] = qh;
    __syncthreads();
    if (r == 0) {
        float s0 = sa[0][pos * 2], s1 = sa[0][pos * 2 + 1];
        float q0 = sb[0][pos * 2], q1 = sb[0][pos * 2 + 1];
#pragma unroll
        for (int j = 1; j < RG; j++) {
            s0 += sa[j][pos * 2]; s1 += sa[j][pos * 2 + 1];
            q0 += sb[j][pos * 2]; q1 += sb[j][pos * 2 + 1];
        }
        g_ps[blockIdx.x * 128 + pos * 2]     = s0;
        g_ps[blockIdx.x * 128 + pos * 2 + 1] = s1;
        g_pq[blockIdx.x * 128 + pos * 2]     = q0;
        g_pq[blockIdx.x * 128 + pos * 2 + 1] = q1;
    }
}

// PARALLEL finisher: ONE BLOCK PER CHANNEL (grid = CH, block = 256).
template <int CH, bool MAP>
__global__ void k_fin(const float* __restrict__ gamma,
                      const float* __restrict__ beta,
                      float* __restrict__ scl, float* __restrict__ bia, int N) {
    const int c = blockIdx.x;
    const int t = threadIdx.x;
    float s = g_ps[t * CH + c] + g_ps[(t + 256) * CH + c];
    float q = g_pq[t * CH + c] + g_pq[(t + 256) * CH + c];
    __shared__ float sh[256];
    __shared__ float shq[256];
    sh[t] = s; shq[t] = q;
    __syncthreads();
#pragma unroll
    for (int w = 128; w >= 1; w >>= 1) {
        if (t < w) { sh[t] += sh[t + w]; shq[t] += shq[t + w]; }
        __syncthreads();
    }
    if (t == 0) {
        float mu  = sh[0] / (float)N;
        float var = shq[0] / (float)N - mu * mu;
        if (var < 0.f) var = 0.f;
        float rs = rsqrtf(var + 1e-4f);
        int tc = c;
        if (MAP) {
            int cc = c >> 5, wi = c & 31, qn = wi >> 1, e = wi & 1;
            tc = cc * 32 + ipslot(qn) * 2 + e;
        }
        float sc = gamma[tc] * rs;
        scl[c] = sc;
        bia[c] = beta[tc] - mu * sc;
    }
}

// weight pack: transpose-to-[n][k], fp16, pslot layout, STRIDE-24 planes
__global__ void k_wcvt(const float* __restrict__ W1, const float* __restrict__ W2,
                       const float* __restrict__ Wn) {
    const int T1 = KK * 2 * 128 * 16;
    const int T2 = T1 + KK * 4 * 128 * 16;
    const int T3 = T2 + 2 * 128 * 16;
    int idx = blockIdx.x * blockDim.x + threadIdx.x;
    if (idx >= T3) return;
    const float* src; uint32_t* dst; int n, p;
    if (idx < T1) {
        int k = idx / (2 * 128 * 16), r = idx % (2 * 128 * 16);
        int ch = r / (128 * 16), r2 = r % (128 * 16);
        n = r2 / 16; p = r2 % 16;
        src = W1 + (size_t)k * 64 * 128 + (size_t)(ch * 32 + 2 * p) * 128 + n;
        dst = g_W1p + (size_t)(k * 2 + ch) * 3072;
    } else if (idx < T2) {
        int i2 = idx - T1;
        int k = i2 / (4 * 128 * 16), r = i2 % (4 * 128 * 16);
        int ch = r / (128 * 16), r2 = r % (128 * 16);
        n = r2 / 16; p = r2 % 16;
        src = W2 + (size_t)k * 128 * 128 + (size_t)(ch * 32 + 2 * p) * 128 + n;
        dst = g_Wcat + (size_t)(2 + k * 4 + ch) * 3072;
    } else {
        int i2 = idx - T2;
        int ch = i2 / (128 * 16), r2 = i2 % (128 * 16);
        n = r2 / 16; p = r2 % 16;
        src = Wn + (size_t)(ch * 32 + 2 * p) * 128 + n;
        dst = g_Wcat + (size_t)ch * 3072;
    }
    float w0 = src[0], w1 = src[128];
    __half h0 = __float2half(w0);
    __half h1 = __float2half(w1);
    uint32_t hp = ((uint32_t)*(unsigned short*)&h1 << 16) |
                  (uint32_t)*(unsigned short*)&h0;
    dst[n * 24 + pslot(p)] = hp;
}

// ---------------- fat-stage gather-GEMM conv kernel --------------------------
// MODE 1: mraw = sum_k a16[gidx_k] @ W1[k]                 (27 stages, fp16)
// MODE 2: out  = f16 @ Wnin + sum_k m16[gidx_k] @ W2[k]    (55 stages, fp32)
// Stage = 64 channels (2 stride-24 planes). A double-buffered (h-plane at
// +3076 for conflict-free stores), B double-buffered cp.async (24KB slots).
// One barrier + one cp.async group per stage. All LDS conflict-free.

#define APL    3076                       // A plane stride (u32): 3072 + 4
#define ABUF   (2 * APL)                  // A u32 per buffer
#define ABYTES (2 * ABUF * 4)             // both A buffers = 49216 B
#define BPL    3072                       // B plane stride (u32)
#define BSLOT  (2 * BPL)                  // B u32 per stage = 6144
#define SMEMB  (ABYTES + 2 * BSLOT * 4)   // 49216 + 49152 = 98368 B

template <int MODE>
__global__ void __launch_bounds__(256, 2) k_conv(
    const uint32_t* __restrict__ src32, uint32_t* __restrict__ mid32,
    float* __restrict__ outp, int N) {

    constexpr int S = (MODE == 1) ? KK : (1 + KK * 2);

    extern __shared__ char sm[];
    const uint32_t smb = smem_u32(sm);
    const uint32_t bbase = smb + (uint32_t)ABYTES;

    const int tid = threadIdx.x;
    const int wid = tid >> 5, lane = tid & 31;
    const int qr = lane >> 2, qc = lane & 3;
    const int wm = wid >> 1, wn = wid & 1;
    const int tile = blockIdx.x * 128;
    const int r = tid >> 1, h = tid & 1;
    const int site = tile + r;

    float acc[2][8][4];
#pragma unroll
    for (int a = 0; a < 2; a++)
#pragma unroll
        for (int b = 0; b < 8; b++)
#pragma unroll
            for (int c = 0; c < 4; c++) acc[a][b][c] = 0.f;

    auto rowOf = [&](int s) -> int {
        if (site >= N) return -1;
        if (MODE == 2) {
            if (s < 1) return site;                          // NiN dense
            return g_gidx[(size_t)((s - 1) >> 1) * N + site];
        }
        return g_gidx[(size_t)s * N + site];
    };

    uint4 rA2[4];           // staged A: 16 u32 = this thread's half-row plane
    int   srA, srN;

    auto ldA = [&](int s, int sr) {
        const uint32_t* sp; int stride, c16;
        if (MODE == 1)          { sp = src32; stride = 32; c16 = h * 16; }
        else if (s < 1)         { sp = g_f16; stride = 32; c16 = h * 16; }
        else                    { sp = src32; stride = 64;
                                  c16 = ((s - 1) & 1) * 32 + h * 16; }
        const uint4* rp = (const uint4*)(sp + (size_t)sr * stride + c16);
        if (sr >= 0) {
#pragma unroll
            for (int j = 0; j < 4; j++) rA2[j] = rp[j];
        }
    };
    auto stA = [&](int buf) {
        uint32_t* Ab = (uint32_t*)sm + buf * ABUF + h * APL + r * 24;
        if (srA >= 0) {
#pragma unroll
            for (int j = 0; j < 4; j++) *(uint4*)(Ab + j * 4) = rA2[j];
        } else {
            uint4 z = make_uint4(0u, 0u, 0u, 0u);
#pragma unroll
            for (int j = 0; j < 4; j++) *(uint4*)(Ab + j * 4) = z;
        }
    };
    auto cpB = [&](int s, int slot) {
        const uint32_t* bp = (MODE == 1) ? (g_W1p + (size_t)s * BSLOT)
                                         : (g_Wcat + (size_t)s * BSLOT);
        uint32_t dst = bbase + (uint32_t)slot * (BSLOT * 4) + (uint32_t)tid * 16;
        const char* srcp = (const char*)bp + (size_t)tid * 16;
#pragma unroll
        for (int j = 0; j < 6; j++)
            asm volatile("cp.async.cg.shared.global [%0], [%1], 16;"
                         :: "r"(dst + (uint32_t)j * 4096u),
                            "l"(srcp + (size_t)j * 4096) : "memory");
    };

    // ---- prologue: B(0) in flight; A(0) stored; A(1) staged ---------------
    cpB(0, 0);
    asm volatile("cp.async.commit_group;" ::: "memory");
    srA = rowOf(0);
    ldA(0, srA);
    stA(0);
    srN = (S > 1) ? rowOf(1) : -1;
    if (S > 1) { ldA(1, srN); }
    srA = srN;
    srN = (S > 2) ? rowOf(2) : -1;
    asm volatile("cp.async.wait_group 0;" ::: "memory");   // B(0) landed
    __syncthreads();

    // ---- main loop: one barrier + one group per stage ---------------------
    for (int s = 0; s < S; s++) {
        // issue B(s+1) into slot (s+1)&1 (ex-MMA(s-1) slot; barrier passed)
        if (s + 1 < S) cpB(s + 1, (s + 1) & 1);
        asm volatile("cp.async.commit_group;" ::: "memory");
        asm volatile("cp.async.wait_group 1;" ::: "memory"); // B(s) landed

        const uint32_t* Ab = (const uint32_t*)sm + (s & 1) * ABUF;
        const uint32_t* Bb = (const uint32_t*)(sm + ABYTES) + (s & 1) * BSLOT;

        // MMA: 2 chunk planes x 2 k16 steps x (2M x 8N)
#pragma unroll
        for (int g = 0; g < 4; g++) {
            const uint32_t* Ap = Ab + (g >> 1) * APL + (g & 1) * 8;
            const uint32_t* Bp = Bb + (g >> 1) * BPL + (g & 1) * 8;
            uint2 a0[2], a1[2];
#pragma unroll
            for (int mt = 0; mt < 2; mt++) {
                int r0 = wm * 32 + mt * 16 + qr;
                a0[mt] = *(const uint2*)&Ap[r0 * 24 + qc * 2];
                a1[mt] = *(const uint2*)&Ap[(r0 + 8) * 24 + qc * 2];
            }
#pragma unroll
            for (int nt = 0; nt < 8; nt++) {
                int c0b = wn * 64 + nt * 8 + qr;
                uint2 bf = *(const uint2*)&Bp[c0b * 24 + qc * 2];
                mma_f16(acc[0][nt], a0[0], a1[0], bf);
                mma_f16(acc[1][nt], a0[1], a1[1], bf);
            }
        }

        // STS A(s+1) from staged regs into buf (s+1)&1 (not read this stage)
        if (s + 1 < S) stA((s + 1) & 1);
        // LDG A(s+2) -> staged regs
        if (s + 2 < S) {
            ldA(s + 2, srN);
            srA = srN;
            if (s + 3 < S) srN = rowOf(s + 3);
        }
        __syncthreads();
    }

    // ---- epilogue ---------------------------------------------------------
#pragma unroll
    for (int mt = 0; mt < 2; mt++) {
        int r0 = wm * 32 + mt * 16 + qr;
        int sA = tile + r0, sB = tile + r0 + 8;
#pragma unroll
        for (int nt = 0; nt < 8; nt++) {
            if (MODE == 1) {
                int P = wn * 32 + nt * 4 + qc;
                int pos = (P >> 4) * 16 + pslot(P & 15);
                if (sA < N)
                    mid32[(size_t)sA * 64 + pos] =
                        cvt2(acc[mt][nt][0], acc[mt][nt][1]);
                if (sB < N)
                    mid32[(size_t)sB * 64 + pos] =
                        cvt2(acc[mt][nt][2], acc[mt][nt][3]);
            } else {
                int col = wn * 64 + nt * 8 + qc * 2;
                if (sA < N)
                    *(float2*)(outp + (size_t)sA * BB + col) =
                        make_float2(acc[mt][nt][0], acc[mt][nt][1]);
                if (sB < N)
                    *(float2*)(outp + (size_t)sB * BB + col) =
                        make_float2(acc[mt][nt][2], acc[mt][nt][3]);
            }
        }
    }
}

// ---------------------------------------------------------------------------
extern "C" void kernel_launch(void* const* d_in, const int* in_sizes, int n_in,
                              void* d_out, int out_size) {
    const float* feat   = (const float*)d_in[0];
    const float* gamma1 = (const float*)d_in[1];
    const float* beta1  = (const float*)d_in[2];
    const float* W1     = (const float*)d_in[3];
    const float* gamma2 = (const float*)d_in[4];
    const float* beta2  = (const float*)d_in[5];
    const float* W2     = (const float*)d_in[6];
    const float* Wnin   = (const float*)d_in[7];
    const int*   nbr    = (const int*)d_in[8];
    const void*  mask   = d_in[9];
    float*       out    = (float*)d_out;

    const int N = in_sizes[0] / AA;

    float *p_s1, *p_b1, *p_s2, *p_b2;
    uint32_t *p_a16, *p_m16, *p_mraw;
    cudaGetSymbolAddress((void**)&p_s1,   g_s1);
    cudaGetSymbolAddress((void**)&p_b1,   g_b1);
    cudaGetSymbolAddress((void**)&p_s2,   g_s2);
    cudaGetSymbolAddress((void**)&p_b2,   g_b2);
    cudaGetSymbolAddress((void**)&p_a16,  g_a16);
    cudaGetSymbolAddress((void**)&p_m16,  g_m16);
    cudaGetSymbolAddress((void**)&p_mraw, g_mraw);

    cudaFuncSetAttribute(k_conv<1>,
                         cudaFuncAttributeMaxDynamicSharedMemorySize, SMEMB);
    cudaFuncSetAttribute(k_conv<2>,
                         cudaFuncAttributeMaxDynamicSharedMemorySize, SMEMB);

    const int gtiles = (N + 127) / 128;
    const int wtot   = KK * 2 * 128 * 16 + KK * 4 * 128 * 16 + 2 * 128 * 16;
    const int n16    = N * 16;    // float4s in feat
    const int n32    = N * 32;    // uint2s in mid

    // prep: gather index (with fused mask detect), weight pack
    k_gidx<<<(N + 255) / 256, 256>>>(nbr, mask, N);
    k_wcvt<<<(wtot + 255) / 256, 256>>>(W1, W2, Wnin);

    // BN1: stats on fp32 feat -> parallel folded affine -> fused apply
    k_stats<AA, 4><<<PB, dim3(AA, 4)>>>(feat, N);
    k_fin<AA, false><<<AA, 256>>>(gamma1, beta1, p_s1, p_b1, N);
    k_bn1<<<(n16 + 255) / 256, 256>>>(feat, p_s1, p_b1, n16);

    // conv1 (27 fat stages) -> g_mraw (fp16, permuted)
    k_conv<1><<<gtiles, 256, SMEMB>>>(p_a16, p_mraw, nullptr, N);

    // BN2: stats on fp16 mid -> parallel folded affine (gamma mapped) -> apply
    k_stats16<4><<<PB, dim3(64, 4)>>>(N);
    k_fin<BB, true><<<BB, 256>>>(gamma2, beta2, p_s2, p_b2, N);
    k_bn2<<<(n32 + 255) / 256, 256>>>(p_s2, p_b2, n32);

    // conv2 (1 NiN + 54 fat stages) -> out (write-once fp32)
    k_conv<2><<<gtiles, 256, SMEMB>>>(p_m16, nullptr, out, N);
}